// round 15
// baseline (speedup 1.0000x reference)
#include <cuda_runtime.h>
#include <cuda_fp16.h>
#include <cstdint>

#define N_NODES 100000
#define N_EDGES 1250000
#define IN_CH   128
#define HID_CH  64
#define CLS_CH  32
#define SCAN_B  1024
#define NB      98        // ceil(N_NODES / SCAN_B)

#define BM 128
#define BK 16
#define SA_PAD 136
#define G1_BLOCKS_TOTAL ((N_NODES + BM - 1) / BM)     // 782
#define G1A_BLOCKS 391                                 // rows [0, 50048)
#define G1B_BLOCKS (G1_BLOCKS_TOTAL - G1A_BLOCKS)      // 391
#define G1B_ROW0   (G1A_BLOCKS * BM)                   // 50048
#define HIST_BLOCKS ((N_EDGES + 255) / 256)            // 4883

// ---------------- scratch (device globals; alloc-free rule) ----------------
__device__ __align__(16) __half g_h1h [(size_t)N_NODES * HID_CH];   // fp16 h1
__device__ __align__(16) float  g_act1[(size_t)N_NODES * HID_CH];
__device__ __align__(16) __half g_m2h [(size_t)N_NODES * CLS_CH];   // fp16 m2
__device__ int g_deg   [N_NODES];          // invariant: zero at kernel_launch entry
__device__ int g_incl  [N_NODES];
__device__ int g_off   [N_NODES + 1];
__device__ int g_cursor[N_NODES];
__device__ int g_bsum  [128];
__device__ int g_csr_src[N_EDGES];

// ---------------- packed f32x2 helpers ----------------
__device__ __forceinline__ unsigned long long pack2(float a, float b) {
    unsigned long long r;
    asm("mov.b64 %0, {%1, %2};" : "=l"(r) : "f"(a), "f"(b));
    return r;
}
__device__ __forceinline__ unsigned long long fma2(unsigned long long a,
                                                   unsigned long long b,
                                                   unsigned long long c) {
    unsigned long long d;
    asm("fma.rn.f32x2 %0, %1, %2, %3;" : "=l"(d) : "l"(a), "l"(b), "l"(c));
    return d;
}
__device__ __forceinline__ float2 ull2f2(unsigned long long u) {
    float2 f;
    asm("mov.b64 {%0, %1}, %2;" : "=f"(f.x), "=f"(f.y) : "l"(u));
    return f;
}
__device__ __forceinline__ float2 h2f2(unsigned int u) {
    __half2 h = *reinterpret_cast<__half2*>(&u);
    return __half22float2(h);
}
__device__ __forceinline__ unsigned int f2h2(float lo, float hi) {
    __half2 h = __floats2half2_rn(lo, hi);
    return *reinterpret_cast<unsigned int*>(&h);
}

// ---------------- gemm1 body: rows [row0, row0+128) of h1 = x @ W1, fp16 out ----------------
__device__ __forceinline__ void gemm1_body(int row0, const float* __restrict__ x,
                                           const float* __restrict__ W1) {
    __shared__ __align__(16) float sA[2][BK][SA_PAD];    // 17.4 KB, k-major
    __shared__ __align__(16) float sW[2][BK][HID_CH];    // 8 KB
    int tid = threadIdx.x;
    int tx = tid & 15;         // cols tx*4 .. +3
    int ty = tid >> 4;         // rows ty*8 .. +7
    int ar = tid >> 2, ac4 = tid & 3;
    int wk = tid >> 4, wc4 = tid & 15;
    int gr0 = min(row0 + ar,      N_NODES - 1);
    int gr1 = min(row0 + ar + 64, N_NODES - 1);
    const float4* xr0 = reinterpret_cast<const float4*>(x + (size_t)gr0 * IN_CH) + ac4;
    const float4* xr1 = reinterpret_cast<const float4*>(x + (size_t)gr1 * IN_CH) + ac4;

    float4 pa0, pa1, pw;
    pa0 = __ldg(xr0);
    pa1 = __ldg(xr1);
    pw  = __ldg(reinterpret_cast<const float4*>(W1 + (size_t)wk * HID_CH) + wc4);

    unsigned long long acc[4][4];
#pragma unroll
    for (int i = 0; i < 4; i++)
#pragma unroll
        for (int j = 0; j < 4; j++) acc[i][j] = 0ull;

#pragma unroll 1
    for (int ch = 0; ch < IN_CH / BK; ch++) {
        int s = ch & 1;
        sA[s][ac4 * 4 + 0][ar] = pa0.x;
        sA[s][ac4 * 4 + 1][ar] = pa0.y;
        sA[s][ac4 * 4 + 2][ar] = pa0.z;
        sA[s][ac4 * 4 + 3][ar] = pa0.w;
        sA[s][ac4 * 4 + 0][ar + 64] = pa1.x;
        sA[s][ac4 * 4 + 1][ar + 64] = pa1.y;
        sA[s][ac4 * 4 + 2][ar + 64] = pa1.z;
        sA[s][ac4 * 4 + 3][ar + 64] = pa1.w;
        *reinterpret_cast<float4*>(&sW[s][wk][wc4 * 4]) = pw;
        __syncthreads();
        if (ch < IN_CH / BK - 1) {
            int kofs = (ch + 1) * BK;
            pa0 = __ldg(xr0 + kofs / 4);
            pa1 = __ldg(xr1 + kofs / 4);
            pw  = __ldg(reinterpret_cast<const float4*>(
                            W1 + (size_t)(kofs + wk) * HID_CH) + wc4);
        }
#pragma unroll
        for (int k = 0; k < BK; k++) {
            ulonglong2 aA = *reinterpret_cast<const ulonglong2*>(&sA[s][k][ty * 8]);
            ulonglong2 aB = *reinterpret_cast<const ulonglong2*>(&sA[s][k][ty * 8 + 4]);
            float4 wv = *reinterpret_cast<const float4*>(&sW[s][k][tx * 4]);
            unsigned long long w0 = pack2(wv.x, wv.x);
            unsigned long long w1 = pack2(wv.y, wv.y);
            unsigned long long w2 = pack2(wv.z, wv.z);
            unsigned long long w3 = pack2(wv.w, wv.w);
            acc[0][0] = fma2(aA.x, w0, acc[0][0]);
            acc[0][1] = fma2(aA.x, w1, acc[0][1]);
            acc[0][2] = fma2(aA.x, w2, acc[0][2]);
            acc[0][3] = fma2(aA.x, w3, acc[0][3]);
            acc[1][0] = fma2(aA.y, w0, acc[1][0]);
            acc[1][1] = fma2(aA.y, w1, acc[1][1]);
            acc[1][2] = fma2(aA.y, w2, acc[1][2]);
            acc[1][3] = fma2(aA.y, w3, acc[1][3]);
            acc[2][0] = fma2(aB.x, w0, acc[2][0]);
            acc[2][1] = fma2(aB.x, w1, acc[2][1]);
            acc[2][2] = fma2(aB.x, w2, acc[2][2]);
            acc[2][3] = fma2(aB.x, w3, acc[2][3]);
            acc[3][0] = fma2(aB.y, w0, acc[3][0]);
            acc[3][1] = fma2(aB.y, w1, acc[3][1]);
            acc[3][2] = fma2(aB.y, w2, acc[3][2]);
            acc[3][3] = fma2(aB.y, w3, acc[3][3]);
        }
    }
#pragma unroll
    for (int rp = 0; rp < 4; rp++) {
        int r = row0 + ty * 8 + rp * 2;
        float2 c0 = ull2f2(acc[rp][0]), c1 = ull2f2(acc[rp][1]);
        float2 c2 = ull2f2(acc[rp][2]), c3 = ull2f2(acc[rp][3]);
        if (r < N_NODES) {
            uint2 st;
            st.x = f2h2(c0.x, c1.x);
            st.y = f2h2(c2.x, c3.x);
            *reinterpret_cast<uint2*>(g_h1h + (size_t)r * HID_CH + tx * 4) = st;
        }
        if (r + 1 < N_NODES) {
            uint2 st;
            st.x = f2h2(c0.y, c1.y);
            st.y = f2h2(c2.y, c3.y);
            *reinterpret_cast<uint2*>(g_h1h + (size_t)(r + 1) * HID_CH + tx * 4) = st;
        }
    }
}

// ---------------- K1: gemm1a ∥ hist ----------------
__global__ __launch_bounds__(256) void k_g1a_hist(const float* __restrict__ x,
                                                  const float* __restrict__ W1,
                                                  const int* __restrict__ dst) {
    if (blockIdx.x < G1A_BLOCKS) {
        gemm1_body(blockIdx.x * BM, x, W1);
    } else {
        int e = (blockIdx.x - G1A_BLOCKS) * 256 + threadIdx.x;
        if (e < N_EDGES) atomicAdd(&g_deg[__ldg(dst + e)], 1);
    }
}

// ---------------- scan1 ----------------
__global__ __launch_bounds__(SCAN_B) void k_scan1() {
    __shared__ int swarp[32];
    int tid = threadIdx.x;
    int lane = tid & 31, wid = tid >> 5;
    int i = blockIdx.x * SCAN_B + tid;
    int v = (i < N_NODES) ? g_deg[i] : 0;
    int x = v;
#pragma unroll
    for (int o = 1; o < 32; o <<= 1) {
        int n = __shfl_up_sync(0xffffffffu, x, o);
        if (lane >= o) x += n;
    }
    if (lane == 31) swarp[wid] = x;
    __syncthreads();
    if (wid == 0) {
        int w = swarp[lane];
#pragma unroll
        for (int o = 1; o < 32; o <<= 1) {
            int n = __shfl_up_sync(0xffffffffu, w, o);
            if (lane >= o) w += n;
        }
        swarp[lane] = w;
    }
    __syncthreads();
    int incl = x + (wid > 0 ? swarp[wid - 1] : 0);
    if (i < N_NODES) g_incl[i] = incl;
    if (tid == SCAN_B - 1) g_bsum[blockIdx.x] = incl;
}

// ---------------- scan23 ----------------
__global__ __launch_bounds__(SCAN_B) void k_scan23() {
    __shared__ int sred[32];
    __shared__ int s_base;
    int tid = threadIdx.x;
    int v = (tid < blockIdx.x) ? g_bsum[tid] : 0;
#pragma unroll
    for (int o = 16; o; o >>= 1) v += __shfl_down_sync(0xffffffffu, v, o);
    if ((tid & 31) == 0) sred[tid >> 5] = v;
    __syncthreads();
    if (tid < 32) {
        int w = sred[tid];
#pragma unroll
        for (int o = 16; o; o >>= 1) w += __shfl_down_sync(0xffffffffu, w, o);
        if (tid == 0) s_base = w;
    }
    __syncthreads();
    int i = blockIdx.x * SCAN_B + tid;
    if (i < N_NODES) {
        int d = g_deg[i];
        int off = g_incl[i] - d + s_base;
        g_off[i] = off;
        g_cursor[i] = off;
        if (i == N_NODES - 1) g_off[N_NODES] = off + d;
    }
}

// ---------------- K2: gemm1b ∥ fill ----------------
__global__ __launch_bounds__(256) void k_g1b_fill(const float* __restrict__ x,
                                                  const float* __restrict__ W1,
                                                  const int* __restrict__ src,
                                                  const int* __restrict__ dst) {
    if (blockIdx.x < G1B_BLOCKS) {
        gemm1_body(G1B_ROW0 + blockIdx.x * BM, x, W1);
    } else {
        int e = (blockIdx.x - G1B_BLOCKS) * 256 + threadIdx.x;
        if (e < N_EDGES) {
            int d = __ldg(dst + e);
            int pos = atomicAdd(&g_cursor[d], 1);
            g_csr_src[pos] = __ldg(src + e);
        }
    }
}

// ---------------- agg1: act1 = relu(A @ h1 + b1); fp16 gather, 4 edges/warp-load ----------------
// lane = grp*8 + q : grp (0..3) picks edge slot, q (0..7) picks uint4 chunk (8 halves)
__global__ __launch_bounds__(256) void k_agg1(const float* __restrict__ b1) {
    int t = blockIdx.x * 256 + threadIdx.x;
    int node = t >> 5;
    if (node >= N_NODES) return;
    int lane = t & 31;
    int grp = lane >> 3;
    int q   = lane & 7;

    int beg = g_off[node];
    int dg  = g_off[node + 1] - beg;
    if (lane == 0) g_deg[node] = 0;      // restore zero-invariant for next call

    const uint4* h1v = reinterpret_cast<const uint4*>(g_h1h);   // row = 8 uint4
    float a0[8] = {0,0,0,0,0,0,0,0};
    float a1[8] = {0,0,0,0,0,0,0,0};
    float a2[8] = {0,0,0,0,0,0,0,0};
    float a3[8] = {0,0,0,0,0,0,0,0};

    for (int base = 0; base < dg; base += 32) {
        int rem = dg - base;
        int idx = (lane < rem) ? __ldg(g_csr_src + beg + base + lane) : 0;
#pragma unroll
        for (int j = 0; j < 8; j += 4) {
            if (4 * j >= rem) break;     // warp-uniform
            int s0 = __shfl_sync(0xffffffffu, idx, 4 * (j + 0) + grp);
            int s1 = __shfl_sync(0xffffffffu, idx, 4 * (j + 1) + grp);
            int s2 = __shfl_sync(0xffffffffu, idx, 4 * (j + 2) + grp);
            int s3 = __shfl_sync(0xffffffffu, idx, 4 * (j + 3) + grp);
            if (4 * (j + 0) + grp < rem) {
                uint4 v = __ldg(h1v + (size_t)s0 * 8 + q);
                float2 p;
                p = h2f2(v.x); a0[0] += p.x; a0[1] += p.y;
                p = h2f2(v.y); a0[2] += p.x; a0[3] += p.y;
                p = h2f2(v.z); a0[4] += p.x; a0[5] += p.y;
                p = h2f2(v.w); a0[6] += p.x; a0[7] += p.y;
            }
            if (4 * (j + 1) + grp < rem) {
                uint4 v = __ldg(h1v + (size_t)s1 * 8 + q);
                float2 p;
                p = h2f2(v.x); a1[0] += p.x; a1[1] += p.y;
                p = h2f2(v.y); a1[2] += p.x; a1[3] += p.y;
                p = h2f2(v.z); a1[4] += p.x; a1[5] += p.y;
                p = h2f2(v.w); a1[6] += p.x; a1[7] += p.y;
            }
            if (4 * (j + 2) + grp < rem) {
                uint4 v = __ldg(h1v + (size_t)s2 * 8 + q);
                float2 p;
                p = h2f2(v.x); a2[0] += p.x; a2[1] += p.y;
                p = h2f2(v.y); a2[2] += p.x; a2[3] += p.y;
                p = h2f2(v.z); a2[4] += p.x; a2[5] += p.y;
                p = h2f2(v.w); a2[6] += p.x; a2[7] += p.y;
            }
            if (4 * (j + 3) + grp < rem) {
                uint4 v = __ldg(h1v + (size_t)s3 * 8 + q);
                float2 p;
                p = h2f2(v.x); a3[0] += p.x; a3[1] += p.y;
                p = h2f2(v.y); a3[2] += p.x; a3[3] += p.y;
                p = h2f2(v.z); a3[4] += p.x; a3[5] += p.y;
                p = h2f2(v.w); a3[6] += p.x; a3[7] += p.y;
            }
        }
    }
    float A[8];
#pragma unroll
    for (int i = 0; i < 8; i++) {
        A[i] = (a0[i] + a1[i]) + (a2[i] + a3[i]);
        A[i] += __shfl_xor_sync(0xffffffffu, A[i], 8);
        A[i] += __shfl_xor_sync(0xffffffffu, A[i], 16);
    }
    if (grp == 0) {
        float4 blo = __ldg(reinterpret_cast<const float4*>(b1) + q * 2);
        float4 bhi = __ldg(reinterpret_cast<const float4*>(b1) + q * 2 + 1);
        float4 lo, hi;
        lo.x = fmaxf(A[0] + blo.x, 0.f);
        lo.y = fmaxf(A[1] + blo.y, 0.f);
        lo.z = fmaxf(A[2] + blo.z, 0.f);
        lo.w = fmaxf(A[3] + blo.w, 0.f);
        hi.x = fmaxf(A[4] + bhi.x, 0.f);
        hi.y = fmaxf(A[5] + bhi.y, 0.f);
        hi.z = fmaxf(A[6] + bhi.z, 0.f);
        hi.w = fmaxf(A[7] + bhi.w, 0.f);
        float* o = g_act1 + (size_t)node * HID_CH + q * 8;
        *reinterpret_cast<float4*>(o)     = lo;
        *reinterpret_cast<float4*>(o + 4) = hi;
    }
}

// ---------------- gemm2: m2 = act1 @ W2 (64->32), fp16 out ----------------
__global__ __launch_bounds__(256) void k_gemm2(const float* __restrict__ W2) {
    __shared__ __align__(16) float sA[2][BK][SA_PAD];
    __shared__ __align__(16) float sW[2][BK][CLS_CH];
    int tid = threadIdx.x;
    int tx = tid & 15;
    int ty = tid >> 4;
    int row0 = blockIdx.x * BM;
    int ar = tid >> 2, ac4 = tid & 3;
    int wk = tid >> 3, wc4 = tid & 7;
    int gr0 = min(row0 + ar,      N_NODES - 1);
    int gr1 = min(row0 + ar + 64, N_NODES - 1);

    float4 pa0, pa1, pw;
    pa0 = *reinterpret_cast<const float4*>(g_act1 + (size_t)gr0 * HID_CH + ac4 * 4);
    pa1 = *reinterpret_cast<const float4*>(g_act1 + (size_t)gr1 * HID_CH + ac4 * 4);
    if (tid < 128)
        pw = __ldg(reinterpret_cast<const float4*>(W2 + (size_t)wk * CLS_CH) + wc4);

    unsigned long long acc[4][2];
#pragma unroll
    for (int i = 0; i < 4; i++) { acc[i][0] = 0ull; acc[i][1] = 0ull; }

#pragma unroll 1
    for (int ch = 0; ch < HID_CH / BK; ch++) {
        int s = ch & 1;
        sA[s][ac4 * 4 + 0][ar] = pa0.x;
        sA[s][ac4 * 4 + 1][ar] = pa0.y;
        sA[s][ac4 * 4 + 2][ar] = pa0.z;
        sA[s][ac4 * 4 + 3][ar] = pa0.w;
        sA[s][ac4 * 4 + 0][ar + 64] = pa1.x;
        sA[s][ac4 * 4 + 1][ar + 64] = pa1.y;
        sA[s][ac4 * 4 + 2][ar + 64] = pa1.z;
        sA[s][ac4 * 4 + 3][ar + 64] = pa1.w;
        if (tid < 128)
            *reinterpret_cast<float4*>(&sW[s][wk][wc4 * 4]) = pw;
        __syncthreads();
        if (ch < HID_CH / BK - 1) {
            int kofs = (ch + 1) * BK;
            pa0 = *reinterpret_cast<const float4*>(
                g_act1 + (size_t)gr0 * HID_CH + kofs + ac4 * 4);
            pa1 = *reinterpret_cast<const float4*>(
                g_act1 + (size_t)gr1 * HID_CH + kofs + ac4 * 4);
            if (tid < 128)
                pw = __ldg(reinterpret_cast<const float4*>(
                               W2 + (size_t)(kofs + wk) * CLS_CH) + wc4);
        }
#pragma unroll
        for (int k = 0; k < BK; k++) {
            ulonglong2 aA = *reinterpret_cast<const ulonglong2*>(&sA[s][k][ty * 8]);
            ulonglong2 aB = *reinterpret_cast<const ulonglong2*>(&sA[s][k][ty * 8 + 4]);
            float2 wv = *reinterpret_cast<const float2*>(&sW[s][k][tx * 2]);
            unsigned long long w0 = pack2(wv.x, wv.x);
            unsigned long long w1 = pack2(wv.y, wv.y);
            acc[0][0] = fma2(aA.x, w0, acc[0][0]);
            acc[0][1] = fma2(aA.x, w1, acc[0][1]);
            acc[1][0] = fma2(aA.y, w0, acc[1][0]);
            acc[1][1] = fma2(aA.y, w1, acc[1][1]);
            acc[2][0] = fma2(aB.x, w0, acc[2][0]);
            acc[2][1] = fma2(aB.x, w1, acc[2][1]);
            acc[3][0] = fma2(aB.y, w0, acc[3][0]);
            acc[3][1] = fma2(aB.y, w1, acc[3][1]);
        }
    }
#pragma unroll
    for (int rp = 0; rp < 4; rp++) {
        int r = row0 + ty * 8 + rp * 2;
        float2 c0 = ull2f2(acc[rp][0]), c1 = ull2f2(acc[rp][1]);
        if (r < N_NODES)
            *reinterpret_cast<unsigned int*>(g_m2h + (size_t)r * CLS_CH + tx * 2) =
                f2h2(c0.x, c1.x);
        if (r + 1 < N_NODES)
            *reinterpret_cast<unsigned int*>(g_m2h + (size_t)(r + 1) * CLS_CH + tx * 2) =
                f2h2(c0.y, c1.y);
    }
}

// ---------------- agg2: out = sigmoid(A @ m2 + b2); fp16 gather, 8 edges/warp-load ----------------
// lane = grp*4 + q : grp (0..7) picks edge slot, q (0..3) picks uint4 chunk (8 halves)
__global__ __launch_bounds__(256) void k_agg2(const float* __restrict__ b2,
                                              float* __restrict__ out) {
    int t = blockIdx.x * 256 + threadIdx.x;
    int node = t >> 5;
    if (node >= N_NODES) return;
    int lane = t & 31;
    int grp = lane >> 2;     // 0..7
    int q   = lane & 3;      // 0..3

    int beg = g_off[node];
    int dg  = g_off[node + 1] - beg;

    const uint4* m2v = reinterpret_cast<const uint4*>(g_m2h);   // row = 4 uint4
    float a0[8] = {0,0,0,0,0,0,0,0};
    float a1[8] = {0,0,0,0,0,0,0,0};
    float a2[8] = {0,0,0,0,0,0,0,0};
    float a3[8] = {0,0,0,0,0,0,0,0};

    for (int base = 0; base < dg; base += 32) {
        int rem = dg - base;
        int idx = (lane < rem) ? __ldg(g_csr_src + beg + base + lane) : 0;
        // edge slots: 8*t + grp for t = 0..3 -> covers all 32 in one pass
        int s0 = __shfl_sync(0xffffffffu, idx, 8 * 0 + grp);
        int s1 = __shfl_sync(0xffffffffu, idx, 8 * 1 + grp);
        int s2 = __shfl_sync(0xffffffffu, idx, 8 * 2 + grp);
        int s3 = __shfl_sync(0xffffffffu, idx, 8 * 3 + grp);
        if (8 * 0 + grp < rem) {
            uint4 v = __ldg(m2v + (size_t)s0 * 4 + q);
            float2 p;
            p = h2f2(v.x); a0[0] += p.x; a0[1] += p.y;
            p = h2f2(v.y); a0[2] += p.x; a0[3] += p.y;
            p = h2f2(v.z); a0[4] += p.x; a0[5] += p.y;
            p = h2f2(v.w); a0[6] += p.x; a0[7] += p.y;
        }
        if (8 * 1 + grp < rem) {
            uint4 v = __ldg(m2v + (size_t)s1 * 4 + q);
            float2 p;
            p = h2f2(v.x); a1[0] += p.x; a1[1] += p.y;
            p = h2f2(v.y); a1[2] += p.x; a1[3] += p.y;
            p = h2f2(v.z); a1[4] += p.x; a1[5] += p.y;
            p = h2f2(v.w); a1[6] += p.x; a1[7] += p.y;
        }
        if (8 * 2 + grp < rem) {
            uint4 v = __ldg(m2v + (size_t)s2 * 4 + q);
            float2 p;
            p = h2f2(v.x); a2[0] += p.x; a2[1] += p.y;
            p = h2f2(v.y); a2[2] += p.x; a2[3] += p.y;
            p = h2f2(v.z); a2[4] += p.x; a2[5] += p.y;
            p = h2f2(v.w); a2[6] += p.x; a2[7] += p.y;
        }
        if (8 * 3 + grp < rem) {
            uint4 v = __ldg(m2v + (size_t)s3 * 4 + q);
            float2 p;
            p = h2f2(v.x); a3[0] += p.x; a3[1] += p.y;
            p = h2f2(v.y); a3[2] += p.x; a3[3] += p.y;
            p = h2f2(v.z); a3[4] += p.x; a3[5] += p.y;
            p = h2f2(v.w); a3[6] += p.x; a3[7] += p.y;
        }
    }
    float A[8];
#pragma unroll
    for (int i = 0; i < 8; i++) {
        A[i] = (a0[i] + a1[i]) + (a2[i] + a3[i]);
        A[i] += __shfl_xor_sync(0xffffffffu, A[i], 4);
        A[i] += __shfl_xor_sync(0xffffffffu, A[i], 8);
        A[i] += __shfl_xor_sync(0xffffffffu, A[i], 16);
    }
    if (grp == 0) {
        float4 blo = __ldg(reinterpret_cast<const float4*>(b2) + q * 2);
        float4 bhi = __ldg(reinterpret_cast<const float4*>(b2) + q * 2 + 1);
        float4 lo, hi;
        lo.x = 1.f / (1.f + __expf(-(A[0] + blo.x)));
        lo.y = 1.f / (1.f + __expf(-(A[1] + blo.y)));
        lo.z = 1.f / (1.f + __expf(-(A[2] + blo.z)));
        lo.w = 1.f / (1.f + __expf(-(A[3] + blo.w)));
        hi.x = 1.f / (1.f + __expf(-(A[4] + bhi.x)));
        hi.y = 1.f / (1.f + __expf(-(A[5] + bhi.y)));
        hi.z = 1.f / (1.f + __expf(-(A[6] + bhi.z)));
        hi.w = 1.f / (1.f + __expf(-(A[7] + bhi.w)));
        float* o = out + (size_t)node * CLS_CH + q * 8;
        *reinterpret_cast<float4*>(o)     = lo;
        *reinterpret_cast<float4*>(o + 4) = hi;
    }
}

extern "C" void kernel_launch(void* const* d_in, const int* in_sizes, int n_in,
                              void* d_out, int out_size) {
    const float* x  = (const float*)d_in[0];
    const int*   ei = (const int*)  d_in[1];
    const float* W1 = (const float*)d_in[2];
    const float* b1 = (const float*)d_in[3];
    const float* W2 = (const float*)d_in[4];
    const float* b2 = (const float*)d_in[5];
    float* out = (float*)d_out;
    const int* src = ei;
    const int* dst = ei + N_EDGES;

    k_g1a_hist<<<G1A_BLOCKS + HIST_BLOCKS, 256>>>(x, W1, dst);        // gemm1a ∥ hist
    k_scan1<<<NB, SCAN_B>>>();
    k_scan23<<<NB, SCAN_B>>>();
    k_g1b_fill<<<G1B_BLOCKS + HIST_BLOCKS, 256>>>(x, W1, src, dst);   // gemm1b ∥ fill  <- profiled (idx 3)
    k_agg1<<<(N_NODES * 32 + 255) / 256, 256>>>(b1);
    k_gemm2<<<(N_NODES + BM - 1) / BM, 256>>>(W2);
    k_agg2<<<(N_NODES * 32 + 255) / 256, 256>>>(b2, out);
}

// round 17
// speedup vs baseline: 1.3289x; 1.3289x over previous
#include <cuda_runtime.h>
#include <cuda_fp16.h>
#include <cstdint>

#define N_NODES 100000
#define N_EDGES 1250000
#define IN_CH   128
#define HID_CH  64
#define CLS_CH  32
#define SCAN_B  1024
#define NB      98        // ceil(N_NODES / SCAN_B)

#define BM 128
#define BK 16
#define SA_PAD 136
#define G1_BLOCKS_TOTAL ((N_NODES + BM - 1) / BM)     // 782
#define G1A_BLOCKS 391                                 // rows [0, 50048)
#define G1B_BLOCKS (G1_BLOCKS_TOTAL - G1A_BLOCKS)      // 391
#define G1B_ROW0   (G1A_BLOCKS * BM)                   // 50048
#define HIST_BLOCKS ((N_EDGES + 255) / 256)            // 4883

// ---------------- scratch (device globals; alloc-free rule) ----------------
__device__ __align__(16) __half g_h1h [(size_t)N_NODES * HID_CH];   // fp16 h1
__device__ __align__(16) float  g_act1[(size_t)N_NODES * HID_CH];
__device__ __align__(16) __half g_m2h [(size_t)N_NODES * CLS_CH];   // fp16 m2
__device__ int g_deg   [N_NODES];          // invariant: zero at kernel_launch entry
__device__ int g_incl  [N_NODES];
__device__ int g_off   [N_NODES + 1];
__device__ int g_cursor[N_NODES];
__device__ int g_bsum  [128];
__device__ int g_csr_src[N_EDGES];

// ---------------- packed f32x2 helpers ----------------
__device__ __forceinline__ unsigned long long pack2(float a, float b) {
    unsigned long long r;
    asm("mov.b64 %0, {%1, %2};" : "=l"(r) : "f"(a), "f"(b));
    return r;
}
__device__ __forceinline__ unsigned long long fma2(unsigned long long a,
                                                   unsigned long long b,
                                                   unsigned long long c) {
    unsigned long long d;
    asm("fma.rn.f32x2 %0, %1, %2, %3;" : "=l"(d) : "l"(a), "l"(b), "l"(c));
    return d;
}
__device__ __forceinline__ float2 ull2f2(unsigned long long u) {
    float2 f;
    asm("mov.b64 {%0, %1}, %2;" : "=f"(f.x), "=f"(f.y) : "l"(u));
    return f;
}
__device__ __forceinline__ float2 h2f2(unsigned int u) {
    __half2 h = *reinterpret_cast<__half2*>(&u);
    return __half22float2(h);
}
__device__ __forceinline__ unsigned int f2h2(float lo, float hi) {
    __half2 h = __floats2half2_rn(lo, hi);
    return *reinterpret_cast<unsigned int*>(&h);
}

// ---------------- gemm1 body: rows [row0, row0+128) of h1 = x @ W1, fp16 out ----------------
__device__ __forceinline__ void gemm1_body(int row0, const float* __restrict__ x,
                                           const float* __restrict__ W1) {
    __shared__ __align__(16) float sA[2][BK][SA_PAD];    // 17.4 KB, k-major
    __shared__ __align__(16) float sW[2][BK][HID_CH];    // 8 KB
    int tid = threadIdx.x;
    int tx = tid & 15;         // cols tx*4 .. +3
    int ty = tid >> 4;         // rows ty*8 .. +7
    int ar = tid >> 2, ac4 = tid & 3;
    int wk = tid >> 4, wc4 = tid & 15;
    int gr0 = min(row0 + ar,      N_NODES - 1);
    int gr1 = min(row0 + ar + 64, N_NODES - 1);
    const float4* xr0 = reinterpret_cast<const float4*>(x + (size_t)gr0 * IN_CH) + ac4;
    const float4* xr1 = reinterpret_cast<const float4*>(x + (size_t)gr1 * IN_CH) + ac4;

    float4 pa0, pa1, pw;
    pa0 = __ldg(xr0);
    pa1 = __ldg(xr1);
    pw  = __ldg(reinterpret_cast<const float4*>(W1 + (size_t)wk * HID_CH) + wc4);

    unsigned long long acc[4][4];
#pragma unroll
    for (int i = 0; i < 4; i++)
#pragma unroll
        for (int j = 0; j < 4; j++) acc[i][j] = 0ull;

#pragma unroll 1
    for (int ch = 0; ch < IN_CH / BK; ch++) {
        int s = ch & 1;
        sA[s][ac4 * 4 + 0][ar] = pa0.x;
        sA[s][ac4 * 4 + 1][ar] = pa0.y;
        sA[s][ac4 * 4 + 2][ar] = pa0.z;
        sA[s][ac4 * 4 + 3][ar] = pa0.w;
        sA[s][ac4 * 4 + 0][ar + 64] = pa1.x;
        sA[s][ac4 * 4 + 1][ar + 64] = pa1.y;
        sA[s][ac4 * 4 + 2][ar + 64] = pa1.z;
        sA[s][ac4 * 4 + 3][ar + 64] = pa1.w;
        *reinterpret_cast<float4*>(&sW[s][wk][wc4 * 4]) = pw;
        __syncthreads();
        if (ch < IN_CH / BK - 1) {
            int kofs = (ch + 1) * BK;
            pa0 = __ldg(xr0 + kofs / 4);
            pa1 = __ldg(xr1 + kofs / 4);
            pw  = __ldg(reinterpret_cast<const float4*>(
                            W1 + (size_t)(kofs + wk) * HID_CH) + wc4);
        }
#pragma unroll
        for (int k = 0; k < BK; k++) {
            ulonglong2 aA = *reinterpret_cast<const ulonglong2*>(&sA[s][k][ty * 8]);
            ulonglong2 aB = *reinterpret_cast<const ulonglong2*>(&sA[s][k][ty * 8 + 4]);
            float4 wv = *reinterpret_cast<const float4*>(&sW[s][k][tx * 4]);
            unsigned long long w0 = pack2(wv.x, wv.x);
            unsigned long long w1 = pack2(wv.y, wv.y);
            unsigned long long w2 = pack2(wv.z, wv.z);
            unsigned long long w3 = pack2(wv.w, wv.w);
            acc[0][0] = fma2(aA.x, w0, acc[0][0]);
            acc[0][1] = fma2(aA.x, w1, acc[0][1]);
            acc[0][2] = fma2(aA.x, w2, acc[0][2]);
            acc[0][3] = fma2(aA.x, w3, acc[0][3]);
            acc[1][0] = fma2(aA.y, w0, acc[1][0]);
            acc[1][1] = fma2(aA.y, w1, acc[1][1]);
            acc[1][2] = fma2(aA.y, w2, acc[1][2]);
            acc[1][3] = fma2(aA.y, w3, acc[1][3]);
            acc[2][0] = fma2(aB.x, w0, acc[2][0]);
            acc[2][1] = fma2(aB.x, w1, acc[2][1]);
            acc[2][2] = fma2(aB.x, w2, acc[2][2]);
            acc[2][3] = fma2(aB.x, w3, acc[2][3]);
            acc[3][0] = fma2(aB.y, w0, acc[3][0]);
            acc[3][1] = fma2(aB.y, w1, acc[3][1]);
            acc[3][2] = fma2(aB.y, w2, acc[3][2]);
            acc[3][3] = fma2(aB.y, w3, acc[3][3]);
        }
    }
#pragma unroll
    for (int rp = 0; rp < 4; rp++) {
        int r = row0 + ty * 8 + rp * 2;
        float2 c0 = ull2f2(acc[rp][0]), c1 = ull2f2(acc[rp][1]);
        float2 c2 = ull2f2(acc[rp][2]), c3 = ull2f2(acc[rp][3]);
        if (r < N_NODES) {
            uint2 st;
            st.x = f2h2(c0.x, c1.x);
            st.y = f2h2(c2.x, c3.x);
            *reinterpret_cast<uint2*>(g_h1h + (size_t)r * HID_CH + tx * 4) = st;
        }
        if (r + 1 < N_NODES) {
            uint2 st;
            st.x = f2h2(c0.y, c1.y);
            st.y = f2h2(c2.y, c3.y);
            *reinterpret_cast<uint2*>(g_h1h + (size_t)(r + 1) * HID_CH + tx * 4) = st;
        }
    }
}

// ---------------- K1: gemm1a ∥ hist ----------------
__global__ __launch_bounds__(256) void k_g1a_hist(const float* __restrict__ x,
                                                  const float* __restrict__ W1,
                                                  const int* __restrict__ dst) {
    if (blockIdx.x < G1A_BLOCKS) {
        gemm1_body(blockIdx.x * BM, x, W1);
    } else {
        int e = (blockIdx.x - G1A_BLOCKS) * 256 + threadIdx.x;
        if (e < N_EDGES) atomicAdd(&g_deg[__ldg(dst + e)], 1);
    }
}

// ---------------- scan1 ----------------
__global__ __launch_bounds__(SCAN_B) void k_scan1() {
    __shared__ int swarp[32];
    int tid = threadIdx.x;
    int lane = tid & 31, wid = tid >> 5;
    int i = blockIdx.x * SCAN_B + tid;
    int v = (i < N_NODES) ? g_deg[i] : 0;
    int x = v;
#pragma unroll
    for (int o = 1; o < 32; o <<= 1) {
        int n = __shfl_up_sync(0xffffffffu, x, o);
        if (lane >= o) x += n;
    }
    if (lane == 31) swarp[wid] = x;
    __syncthreads();
    if (wid == 0) {
        int w = swarp[lane];
#pragma unroll
        for (int o = 1; o < 32; o <<= 1) {
            int n = __shfl_up_sync(0xffffffffu, w, o);
            if (lane >= o) w += n;
        }
        swarp[lane] = w;
    }
    __syncthreads();
    int incl = x + (wid > 0 ? swarp[wid - 1] : 0);
    if (i < N_NODES) g_incl[i] = incl;
    if (tid == SCAN_B - 1) g_bsum[blockIdx.x] = incl;
}

// ---------------- scan23 ----------------
__global__ __launch_bounds__(SCAN_B) void k_scan23() {
    __shared__ int sred[32];
    __shared__ int s_base;
    int tid = threadIdx.x;
    int v = (tid < blockIdx.x) ? g_bsum[tid] : 0;
#pragma unroll
    for (int o = 16; o; o >>= 1) v += __shfl_down_sync(0xffffffffu, v, o);
    if ((tid & 31) == 0) sred[tid >> 5] = v;
    __syncthreads();
    if (tid < 32) {
        int w = sred[tid];
#pragma unroll
        for (int o = 16; o; o >>= 1) w += __shfl_down_sync(0xffffffffu, w, o);
        if (tid == 0) s_base = w;
    }
    __syncthreads();
    int i = blockIdx.x * SCAN_B + tid;
    if (i < N_NODES) {
        int d = g_deg[i];
        int off = g_incl[i] - d + s_base;
        g_off[i] = off;
        g_cursor[i] = off;
        if (i == N_NODES - 1) g_off[N_NODES] = off + d;
    }
}

// ---------------- K2: gemm1b ∥ fill ----------------
__global__ __launch_bounds__(256) void k_g1b_fill(const float* __restrict__ x,
                                                  const float* __restrict__ W1,
                                                  const int* __restrict__ src,
                                                  const int* __restrict__ dst) {
    if (blockIdx.x < G1B_BLOCKS) {
        gemm1_body(G1B_ROW0 + blockIdx.x * BM, x, W1);
    } else {
        int e = (blockIdx.x - G1B_BLOCKS) * 256 + threadIdx.x;
        if (e < N_EDGES) {
            int d = __ldg(dst + e);
            int pos = atomicAdd(&g_cursor[d], 1);
            g_csr_src[pos] = __ldg(src + e);
        }
    }
}

// ---------------- agg1: act1 = relu(A @ h1 + b1); fp16 gather, R14 structure ----------------
// lane = half*16 + q : half picks edge parity, q picks uint2 chunk (ch 4q..4q+3)
__global__ __launch_bounds__(256) void k_agg1(const float* __restrict__ b1) {
    int t = blockIdx.x * 256 + threadIdx.x;
    int node = t >> 5;
    if (node >= N_NODES) return;
    int lane = t & 31;
    int half = lane >> 4;
    int q    = lane & 15;

    int beg = g_off[node];
    int dg  = g_off[node + 1] - beg;
    if (lane == 0) g_deg[node] = 0;      // restore zero-invariant for next call

    const uint2* h1v = reinterpret_cast<const uint2*>(g_h1h);   // row = 16 uint2
    float4 a0{0,0,0,0}, a1{0,0,0,0}, a2{0,0,0,0}, a3{0,0,0,0};

    for (int base = 0; base < dg; base += 32) {
        int rem = dg - base;
        int idx = (lane < rem) ? __ldg(g_csr_src + beg + base + lane) : 0;
#pragma unroll
        for (int j = 0; j < 16; j += 4) {
            if (2 * j >= rem) break;     // warp-uniform
            int s0 = __shfl_sync(0xffffffffu, idx, 2 * j + 0 + half);
            int s1 = __shfl_sync(0xffffffffu, idx, 2 * j + 2 + half);
            int s2 = __shfl_sync(0xffffffffu, idx, 2 * j + 4 + half);
            int s3 = __shfl_sync(0xffffffffu, idx, 2 * j + 6 + half);
            if (2 * j + 0 + half < rem) {
                uint2 v = __ldg(h1v + (size_t)s0 * 16 + q);
                float2 p0 = h2f2(v.x), p1 = h2f2(v.y);
                a0.x += p0.x; a0.y += p0.y; a0.z += p1.x; a0.w += p1.y;
            }
            if (2 * j + 2 + half < rem) {
                uint2 v = __ldg(h1v + (size_t)s1 * 16 + q);
                float2 p0 = h2f2(v.x), p1 = h2f2(v.y);
                a1.x += p0.x; a1.y += p0.y; a1.z += p1.x; a1.w += p1.y;
            }
            if (2 * j + 4 + half < rem) {
                uint2 v = __ldg(h1v + (size_t)s2 * 16 + q);
                float2 p0 = h2f2(v.x), p1 = h2f2(v.y);
                a2.x += p0.x; a2.y += p0.y; a2.z += p1.x; a2.w += p1.y;
            }
            if (2 * j + 6 + half < rem) {
                uint2 v = __ldg(h1v + (size_t)s3 * 16 + q);
                float2 p0 = h2f2(v.x), p1 = h2f2(v.y);
                a3.x += p0.x; a3.y += p0.y; a3.z += p1.x; a3.w += p1.y;
            }
        }
    }
    float4 A;
    A.x = (a0.x + a1.x) + (a2.x + a3.x);
    A.y = (a0.y + a1.y) + (a2.y + a3.y);
    A.z = (a0.z + a1.z) + (a2.z + a3.z);
    A.w = (a0.w + a1.w) + (a2.w + a3.w);
    A.x += __shfl_xor_sync(0xffffffffu, A.x, 16);
    A.y += __shfl_xor_sync(0xffffffffu, A.y, 16);
    A.z += __shfl_xor_sync(0xffffffffu, A.z, 16);
    A.w += __shfl_xor_sync(0xffffffffu, A.w, 16);
    if (half == 0) {
        float4 b = __ldg(reinterpret_cast<const float4*>(b1) + q);
        A.x = fmaxf(A.x + b.x, 0.f);
        A.y = fmaxf(A.y + b.y, 0.f);
        A.z = fmaxf(A.z + b.z, 0.f);
        A.w = fmaxf(A.w + b.w, 0.f);
        reinterpret_cast<float4*>(g_act1)[(size_t)node * 16 + q] = A;
    }
}

// ---------------- gemm2: m2 = act1 @ W2 (64->32), fp16 out ----------------
__global__ __launch_bounds__(256) void k_gemm2(const float* __restrict__ W2) {
    __shared__ __align__(16) float sA[2][BK][SA_PAD];
    __shared__ __align__(16) float sW[2][BK][CLS_CH];
    int tid = threadIdx.x;
    int tx = tid & 15;
    int ty = tid >> 4;
    int row0 = blockIdx.x * BM;
    int ar = tid >> 2, ac4 = tid & 3;
    int wk = tid >> 3, wc4 = tid & 7;
    int gr0 = min(row0 + ar,      N_NODES - 1);
    int gr1 = min(row0 + ar + 64, N_NODES - 1);

    float4 pa0, pa1, pw;
    pa0 = *reinterpret_cast<const float4*>(g_act1 + (size_t)gr0 * HID_CH + ac4 * 4);
    pa1 = *reinterpret_cast<const float4*>(g_act1 + (size_t)gr1 * HID_CH + ac4 * 4);
    if (tid < 128)
        pw = __ldg(reinterpret_cast<const float4*>(W2 + (size_t)wk * CLS_CH) + wc4);

    unsigned long long acc[4][2];
#pragma unroll
    for (int i = 0; i < 4; i++) { acc[i][0] = 0ull; acc[i][1] = 0ull; }

#pragma unroll 1
    for (int ch = 0; ch < HID_CH / BK; ch++) {
        int s = ch & 1;
        sA[s][ac4 * 4 + 0][ar] = pa0.x;
        sA[s][ac4 * 4 + 1][ar] = pa0.y;
        sA[s][ac4 * 4 + 2][ar] = pa0.z;
        sA[s][ac4 * 4 + 3][ar] = pa0.w;
        sA[s][ac4 * 4 + 0][ar + 64] = pa1.x;
        sA[s][ac4 * 4 + 1][ar + 64] = pa1.y;
        sA[s][ac4 * 4 + 2][ar + 64] = pa1.z;
        sA[s][ac4 * 4 + 3][ar + 64] = pa1.w;
        if (tid < 128)
            *reinterpret_cast<float4*>(&sW[s][wk][wc4 * 4]) = pw;
        __syncthreads();
        if (ch < HID_CH / BK - 1) {
            int kofs = (ch + 1) * BK;
            pa0 = *reinterpret_cast<const float4*>(
                g_act1 + (size_t)gr0 * HID_CH + kofs + ac4 * 4);
            pa1 = *reinterpret_cast<const float4*>(
                g_act1 + (size_t)gr1 * HID_CH + kofs + ac4 * 4);
            if (tid < 128)
                pw = __ldg(reinterpret_cast<const float4*>(
                               W2 + (size_t)(kofs + wk) * CLS_CH) + wc4);
        }
#pragma unroll
        for (int k = 0; k < BK; k++) {
            ulonglong2 aA = *reinterpret_cast<const ulonglong2*>(&sA[s][k][ty * 8]);
            ulonglong2 aB = *reinterpret_cast<const ulonglong2*>(&sA[s][k][ty * 8 + 4]);
            float2 wv = *reinterpret_cast<const float2*>(&sW[s][k][tx * 2]);
            unsigned long long w0 = pack2(wv.x, wv.x);
            unsigned long long w1 = pack2(wv.y, wv.y);
            acc[0][0] = fma2(aA.x, w0, acc[0][0]);
            acc[0][1] = fma2(aA.x, w1, acc[0][1]);
            acc[1][0] = fma2(aA.y, w0, acc[1][0]);
            acc[1][1] = fma2(aA.y, w1, acc[1][1]);
            acc[2][0] = fma2(aB.x, w0, acc[2][0]);
            acc[2][1] = fma2(aB.x, w1, acc[2][1]);
            acc[3][0] = fma2(aB.y, w0, acc[3][0]);
            acc[3][1] = fma2(aB.y, w1, acc[3][1]);
        }
    }
#pragma unroll
    for (int rp = 0; rp < 4; rp++) {
        int r = row0 + ty * 8 + rp * 2;
        float2 c0 = ull2f2(acc[rp][0]), c1 = ull2f2(acc[rp][1]);
        if (r < N_NODES)
            *reinterpret_cast<unsigned int*>(g_m2h + (size_t)r * CLS_CH + tx * 2) =
                f2h2(c0.x, c1.x);
        if (r + 1 < N_NODES)
            *reinterpret_cast<unsigned int*>(g_m2h + (size_t)(r + 1) * CLS_CH + tx * 2) =
                f2h2(c0.y, c1.y);
    }
}

// ---------------- agg2: out = sigmoid(A @ m2 + b2); fp16 gather, R14 structure ----------------
// lane = grp*8 + q : grp picks edge slot, q picks uint2 chunk (ch 4q..4q+3)
__global__ __launch_bounds__(256) void k_agg2(const float* __restrict__ b2,
                                              float* __restrict__ out) {
    int t = blockIdx.x * 256 + threadIdx.x;
    int node = t >> 5;
    if (node >= N_NODES) return;
    int lane = t & 31;
    int grp = lane >> 3;
    int q   = lane & 7;

    int beg = g_off[node];
    int dg  = g_off[node + 1] - beg;

    const uint2* m2v = reinterpret_cast<const uint2*>(g_m2h);   // row = 8 uint2
    float4 a0{0,0,0,0}, a1{0,0,0,0}, a2{0,0,0,0}, a3{0,0,0,0};

    for (int base = 0; base < dg; base += 32) {
        int rem = dg - base;
        int idx = (lane < rem) ? __ldg(g_csr_src + beg + base + lane) : 0;
#pragma unroll
        for (int j = 0; j < 8; j += 4) {
            if (4 * j >= rem) break;     // warp-uniform
            int s0 = __shfl_sync(0xffffffffu, idx, 4 * (j + 0) + grp);
            int s1 = __shfl_sync(0xffffffffu, idx, 4 * (j + 1) + grp);
            int s2 = __shfl_sync(0xffffffffu, idx, 4 * (j + 2) + grp);
            int s3 = __shfl_sync(0xffffffffu, idx, 4 * (j + 3) + grp);
            if (4 * (j + 0) + grp < rem) {
                uint2 v = __ldg(m2v + (size_t)s0 * 8 + q);
                float2 p0 = h2f2(v.x), p1 = h2f2(v.y);
                a0.x += p0.x; a0.y += p0.y; a0.z += p1.x; a0.w += p1.y;
            }
            if (4 * (j + 1) + grp < rem) {
                uint2 v = __ldg(m2v + (size_t)s1 * 8 + q);
                float2 p0 = h2f2(v.x), p1 = h2f2(v.y);
                a1.x += p0.x; a1.y += p0.y; a1.z += p1.x; a1.w += p1.y;
            }
            if (4 * (j + 2) + grp < rem) {
                uint2 v = __ldg(m2v + (size_t)s2 * 8 + q);
                float2 p0 = h2f2(v.x), p1 = h2f2(v.y);
                a2.x += p0.x; a2.y += p0.y; a2.z += p1.x; a2.w += p1.y;
            }
            if (4 * (j + 3) + grp < rem) {
                uint2 v = __ldg(m2v + (size_t)s3 * 8 + q);
                float2 p0 = h2f2(v.x), p1 = h2f2(v.y);
                a3.x += p0.x; a3.y += p0.y; a3.z += p1.x; a3.w += p1.y;
            }
        }
    }
    float4 A;
    A.x = (a0.x + a1.x) + (a2.x + a3.x);
    A.y = (a0.y + a1.y) + (a2.y + a3.y);
    A.z = (a0.z + a1.z) + (a2.z + a3.z);
    A.w = (a0.w + a1.w) + (a2.w + a3.w);
    A.x += __shfl_xor_sync(0xffffffffu, A.x, 8);
    A.y += __shfl_xor_sync(0xffffffffu, A.y, 8);
    A.z += __shfl_xor_sync(0xffffffffu, A.z, 8);
    A.w += __shfl_xor_sync(0xffffffffu, A.w, 8);
    A.x += __shfl_xor_sync(0xffffffffu, A.x, 16);
    A.y += __shfl_xor_sync(0xffffffffu, A.y, 16);
    A.z += __shfl_xor_sync(0xffffffffu, A.z, 16);
    A.w += __shfl_xor_sync(0xffffffffu, A.w, 16);
    if (grp == 0) {
        float4 b = __ldg(reinterpret_cast<const float4*>(b2) + q);
        A.x = 1.f / (1.f + __expf(-(A.x + b.x)));
        A.y = 1.f / (1.f + __expf(-(A.y + b.y)));
        A.z = 1.f / (1.f + __expf(-(A.z + b.z)));
        A.w = 1.f / (1.f + __expf(-(A.w + b.w)));
        reinterpret_cast<float4*>(out)[(size_t)node * 8 + q] = A;
    }
}

extern "C" void kernel_launch(void* const* d_in, const int* in_sizes, int n_in,
                              void* d_out, int out_size) {
    const float* x  = (const float*)d_in[0];
    const int*   ei = (const int*)  d_in[1];
    const float* W1 = (const float*)d_in[2];
    const float* b1 = (const float*)d_in[3];
    const float* W2 = (const float*)d_in[4];
    const float* b2 = (const float*)d_in[5];
    float* out = (float*)d_out;
    const int* src = ei;
    const int* dst = ei + N_EDGES;

    k_g1a_hist<<<G1A_BLOCKS + HIST_BLOCKS, 256>>>(x, W1, dst);        // gemm1a ∥ hist
    k_scan1<<<NB, SCAN_B>>>();
    k_scan23<<<NB, SCAN_B>>>();
    k_g1b_fill<<<G1B_BLOCKS + HIST_BLOCKS, 256>>>(x, W1, src, dst);   // gemm1b ∥ fill  <- profiled (idx 3)
    k_agg1<<<(N_NODES * 32 + 255) / 256, 256>>>(b1);
    k_gemm2<<<(N_NODES + BM - 1) / BM, 256>>>(W2);
    k_agg2<<<(N_NODES * 32 + 255) / 256, 256>>>(b2, out);
}